// round 15
// baseline (speedup 1.0000x reference)
#include <cuda_runtime.h>
#include <cuda_fp16.h>
#include <cstdint>
#include <math.h>

// Problem constants
#define B_  4
#define T_  2048
#define C_  1024
#define H_  16
#define D_  64
#define M_  (B_*T_)   // 8192

// Scratch (allocation-free rule: __device__ globals)
__device__ __half g_Qh[M_ * C_];
__device__ __half g_Kh[M_ * C_];
__device__ __half g_Vh[M_ * C_];
__device__ __half g_xh[M_ * C_];
__device__ __half g_wh[4 * C_ * C_];
__device__ __half g_Oh[M_ * C_];
__device__ int    g_mflag[B_ * 16 * 32];

// ---------------------------------------------------------------------------
// Common PTX helpers
// ---------------------------------------------------------------------------
__device__ __forceinline__ uint32_t smem_u32a(const void* p){
    uint32_t a;
    asm("{ .reg .u64 t; cvta.to.shared.u64 t, %1; cvt.u32.u64 %0, t; }" : "=r"(a) : "l"(p));
    return a;
}
__device__ __forceinline__ void mma16816(float* d, const uint32_t* a, const uint32_t* b){
    asm volatile("mma.sync.aligned.m16n8k16.row.col.f32.f16.f16.f32 "
        "{%0,%1,%2,%3}, {%4,%5,%6,%7}, {%8,%9}, {%0,%1,%2,%3};"
        : "+f"(d[0]), "+f"(d[1]), "+f"(d[2]), "+f"(d[3])
        : "r"(a[0]), "r"(a[1]), "r"(a[2]), "r"(a[3]), "r"(b[0]), "r"(b[1]));
}
__device__ __forceinline__ void ldsm4(uint32_t* r, uint32_t addr){
    asm volatile("ldmatrix.sync.aligned.m8n8.x4.shared.b16 {%0,%1,%2,%3}, [%4];"
        : "=r"(r[0]), "=r"(r[1]), "=r"(r[2]), "=r"(r[3]) : "r"(addr));
}
__device__ __forceinline__ void ldsm4t(uint32_t* r, uint32_t addr){
    asm volatile("ldmatrix.sync.aligned.m8n8.x4.trans.shared.b16 {%0,%1,%2,%3}, [%4];"
        : "=r"(r[0]), "=r"(r[1]), "=r"(r[2]), "=r"(r[3]) : "r"(addr));
}
__device__ __forceinline__ uint32_t packe(float a, float b){
    __half2 h = __floats2half2_rn(a, b);
    return *(uint32_t*)&h;
}
__device__ __forceinline__ float ex2f(float x){
    float y;
    asm("ex2.approx.f32 %0, %1;" : "=f"(y) : "f"(x));
    return y;
}
#define CP16(dst, src) asm volatile("cp.async.cg.shared.global [%0], [%1], 16;" :: "r"(dst), "l"(src))
#define CP_COMMIT()    asm volatile("cp.async.commit_group;")
#define CP_WAIT1()     asm volatile("cp.async.wait_group 1;")
#define CP_WAIT0()     asm volatile("cp.async.wait_group 0;")

// ---------------------------------------------------------------------------
// Merged fp32 -> fp16 convert: x (8M elems) then 4 weights (1M each)
// ---------------------------------------------------------------------------
#define XN_  (M_*C_)        // 8388608
#define WN_  (C_*C_)        // 1048576
__global__ __launch_bounds__(256) void convert_all(const float* __restrict__ x,
                                                   const float* __restrict__ w0,
                                                   const float* __restrict__ w1,
                                                   const float* __restrict__ w2,
                                                   const float* __restrict__ w3,
                                                   __half* __restrict__ xh,
                                                   __half* __restrict__ wh)
{
    long i = ((long)blockIdx.x * 256 + threadIdx.x) * 4;
    const float* src;
    __half* dst;
    if (i < XN_) { src = x + i; dst = xh + i; }
    else {
        long j = i - XN_;
        int z = (int)(j >> 20);
        const float* w = z == 0 ? w0 : (z == 1 ? w1 : (z == 2 ? w2 : w3));
        src = w + (j & (WN_ - 1));
        dst = wh + j;
    }
    float4 v = *(const float4*)src;
    ((__half2*)dst)[0] = __floats2half2_rn(v.x, v.y);
    ((__half2*)dst)[1] = __floats2half2_rn(v.z, v.w);
}

// ---------------------------------------------------------------------------
// Mask pre-scan: flag[b][qb][kb] = 1 iff mask[b, qb*128:+128, kb*64:+64] all != 0
// ---------------------------------------------------------------------------
__global__ __launch_bounds__(256) void mask_flags(const int* __restrict__ mask)
{
    __shared__ int s_zero;
    const int t = threadIdx.x;
    if (t == 0) s_zero = 0;
    __syncthreads();
    const int fid = blockIdx.x;
    const int b  = fid >> 9;
    const int qb = (fid >> 5) & 15;
    const int kb = fid & 31;
    const int* base = mask + ((size_t)b * T_ + qb * 128) * T_ + kb * 64;
    const int r = t >> 1, hh = t & 1;
    const int4* p = (const int4*)(base + (size_t)r * T_ + hh * 32);
    bool ok = true;
#pragma unroll
    for (int i = 0; i < 8; i++) {
        int4 v = p[i];
        ok = ok && (v.x != 0) && (v.y != 0) && (v.z != 0) && (v.w != 0);
    }
    if (!ok) s_zero = 1;
    __syncthreads();
    if (t == 0) g_mflag[fid] = s_zero ? 0 : 1;
}

// ===========================================================================
// GEMM: C[m,n] = sum_k A[m,k]*W[n,k], single-pass fp16 mma.
// CTA 128x128, BK=64, 3-stage cp.async (96KB -> 2 CTAs/SM), 128 threads,
// 4 warps with 64x64 tiles. A fragments double-buffered, B single-buffered.
// blockIdx.z selects weight slice + output (fused QKV).
// ===========================================================================
#define TILE16 16384                  // 128 rows x 128 bytes (64 fp16 cols)
#define NSTG   3
#define STAGE_B (2*TILE16)            // A | B
#define G_SMEM (NSTG*STAGE_B)         // 98304

#define QSCALE 0.18033688011f         // 0.125 * log2(e)

template<bool HALF_OUT>
__global__ __launch_bounds__(128, 2) void gemm_fp16(
    const __half* __restrict__ Ag,
    const __half* __restrict__ Bg,
    void* __restrict__ C0, void* __restrict__ C1, void* __restrict__ C2,
    int M, int N, int K)
{
    extern __shared__ char smem_raw[];
    const uint32_t sb = smem_u32a(smem_raw);

    const int z = blockIdx.z;
    const __half* Bz = Bg + (size_t)z * N * K;
    void* Cout = z == 0 ? C0 : (z == 1 ? C1 : C2);
    const float oscale = (HALF_OUT && z == 0) ? QSCALE : 1.0f;

    const int tid  = threadIdx.x;
    const int w    = tid >> 5;
    const int lane = tid & 31;
    const int wm   = w >> 1;          // 0..1
    const int wn   = w & 1;           // 0..1
    const int m0   = blockIdx.y * 128;
    const int n0   = blockIdx.x * 128;

    auto prefetch = [&](int t, int s){
        uint32_t st = sb + s * STAGE_B;
        int k0 = t * 64;
#pragma unroll
        for (int i = 0; i < 8; i++) {
            int id = i * 128 + tid;          // 0..1023
            int r = id >> 3, c = id & 7;
            uint32_t dsw = (uint32_t)(r * 128 + ((c ^ (r & 7)) << 4));
            CP16(st + dsw,          Ag + (size_t)(m0 + r) * K + k0 + c * 8);
            CP16(st + TILE16 + dsw, Bz + (size_t)(n0 + r) * K + k0 + c * 8);
        }
    };

    prefetch(0, 0); CP_COMMIT();
    prefetch(1, 1); CP_COMMIT();

    float acc[4][8][4];
#pragma unroll
    for (int mi = 0; mi < 4; mi++)
#pragma unroll
        for (int nb = 0; nb < 8; nb++)
#pragma unroll
            for (int j = 0; j < 4; j++) acc[mi][nb][j] = 0.f;

    uint32_t bhf[8][4];               // single-buffered per kp
    uint32_t ahf[2][4][4];            // double-buffered per kk

    const int NT = K / 64;            // 16
    for (int t = 0; t < NT; t++) {
        CP_WAIT1();
        __syncthreads();
        if (t + 2 < NT) prefetch(t + 2, (t + 2) % NSTG);
        CP_COMMIT();                  // uniform group accounting

        const uint32_t aB = sb + (t % NSTG) * STAGE_B;
        const uint32_t bB = aB + TILE16;

        auto ldsmB = [&](int kp){
#pragma unroll
            for (int nb = 0; nb < 8; nb++) {
                int r = wn * 64 + nb * 8 + (lane & 7);
                int c = kp * 4 + (lane >> 3);
                ldsm4(bhf[nb], bB + (uint32_t)(r * 128 + ((c ^ (r & 7)) << 4)));
            }
        };
        auto ldsmA = [&](int kk, uint32_t (*dst)[4]){
#pragma unroll
            for (int mi = 0; mi < 4; mi++) {
                int r = wm * 64 + mi * 16 + (lane & 15);
                int c = kk * 2 + (lane >> 4);
                ldsm4(dst[mi], aB + (uint32_t)(r * 128 + ((c ^ (r & 7)) << 4)));
            }
        };
        auto mma_kk = [&](uint32_t (*af)[4], int k2){
#pragma unroll
            for (int mi = 0; mi < 4; mi++)
#pragma unroll
                for (int nb = 0; nb < 8; nb++)
                    mma16816(acc[mi][nb], af[mi], bhf[nb] + k2 * 2);
        };

        ldsmB(0);
        ldsmA(0, ahf[0]);
        ldsmA(1, ahf[1]);
        mma_kk(ahf[0], 0);            // kk0 (kp0)
        ldsmA(2, ahf[0]);
        mma_kk(ahf[1], 1);            // kk1 (kp0)
        ldsmB(1);
        ldsmA(3, ahf[1]);
        mma_kk(ahf[0], 0);            // kk2 (kp1)
        mma_kk(ahf[1], 1);            // kk3 (kp1)
    }

    // Epilogue: direct register -> global (with optional output scale)
#pragma unroll
    for (int mi = 0; mi < 4; mi++) {
        int r0 = m0 + wm * 64 + mi * 16 + (lane >> 2);
#pragma unroll
        for (int nb = 0; nb < 8; nb++) {
            int col = n0 + wn * 64 + nb * 8 + (lane & 3) * 2;
            if (HALF_OUT) {
                __half* Ch = (__half*)Cout;
                *(__half2*)(Ch + (size_t)r0 * N + col) =
                    __floats2half2_rn(acc[mi][nb][0] * oscale, acc[mi][nb][1] * oscale);
                *(__half2*)(Ch + (size_t)(r0 + 8) * N + col) =
                    __floats2half2_rn(acc[mi][nb][2] * oscale, acc[mi][nb][3] * oscale);
            } else {
                float* Cf = (float*)Cout;
                *(float2*)(Cf + (size_t)r0 * N + col) =
                    make_float2(acc[mi][nb][0], acc[mi][nb][1]);
                *(float2*)(Cf + (size_t)(r0 + 8) * N + col) =
                    make_float2(acc[mi][nb][2], acc[mi][nb][3]);
            }
        }
    }
}

// ===========================================================================
// Register-resident flash attention (raw mma, fp16), fp16 output.
// CTA = (b,h) x 128 q-rows, 128 threads (4 warps x 32 q-rows = 2 m-blocks),
// 128-key KV stages (NKV=2), chunk-ring software pipeline (8 chunks/stage),
// one sync + one wait per 128 keys, 2 CTAs/SM.
// Softmax scale pre-folded into Q (log2 units); row sums via ones-MMA.
// ===========================================================================
#define AT_ROWB 144                   // 72 halves per row
#define OFF_Q   0
#define Q_BYTES (128*AT_ROWB)         // 18432
#define OFF_KV  Q_BYTES
#define KV_ROWS 128
#define KV_STG  (2*KV_ROWS*AT_ROWB)   // 36864 (K 128 rows + V 128 rows)
#define NKV     2
#define ATT_SMEM (OFF_KV + NKV*KV_STG) // 92160

__global__ __launch_bounds__(128, 2) void attn_reg(const __half* __restrict__ Q,
                                                   const __half* __restrict__ K,
                                                   const __half* __restrict__ V,
                                                   const int*    __restrict__ mask,
                                                   __half* __restrict__ Oh)
{
    extern __shared__ char smem_raw[];
    const uint32_t sb = smem_u32a(smem_raw);

    const int tid  = threadIdx.x;
    const int w    = tid >> 5;
    const int lane = tid & 31;
    const int b    = blockIdx.y >> 4;
    const int h    = blockIdx.y & 15;
    const int q0   = blockIdx.x * 128;

    // ---- per-thread prefetch bases (advance by 128*C_ per stage) ----
    const int pr = tid >> 3;                 // 0..15
    const int pc = tid & 7;                  // 0..7
    const __half* kg = K + ((size_t)(b * T_) + pr) * C_ + h * D_ + pc * 8;
    const __half* vg = V + ((size_t)(b * T_) + pr) * C_ + h * D_ + pc * 8;
    const uint32_t soff = (uint32_t)(pr * AT_ROWB + pc * 16);
    const uint32_t stg[NKV] = { sb + OFF_KV, sb + OFF_KV + KV_STG };

    auto prefetch = [&](const __half* kp, const __half* vp, uint32_t sbase){
#pragma unroll
        for (int i = 0; i < 8; i++) {
            CP16(sbase + soff + i * 16 * AT_ROWB,                      kp + (size_t)i * 16 * C_);
            CP16(sbase + KV_ROWS * AT_ROWB + soff + i * 16 * AT_ROWB,  vp + (size_t)i * 16 * C_);
        }
    };

    prefetch(kg, vg, stg[0]); CP_COMMIT();
    const __half* kgn = kg + (size_t)KV_ROWS * C_;
    const __half* vgn = vg + (size_t)KV_ROWS * C_;

    // ---- Q tile: 128 rows (Q already carries 0.125*log2e) ----
#pragma unroll
    for (int i = 0; i < 8; i++) {
        int cid = i * 128 + tid;             // 0..1023
        int r = cid >> 3, c = cid & 7;
        *(uint4*)(smem_raw + OFF_Q + r * AT_ROWB + c * 16) =
            *(const uint4*)(Q + (size_t)(b * T_ + q0 + r) * C_ + h * D_ + c * 8);
    }
    __syncthreads();

    uint32_t qf[2][4][4];                    // 2 m-blocks x 4 kd
#pragma unroll
    for (int m = 0; m < 2; m++)
#pragma unroll
        for (int kd = 0; kd < 4; kd++) {
            uint32_t aq = sb + OFF_Q + (w * 32 + m * 16 + (lane & 15)) * AT_ROWB
                        + (kd * 16 + (lane >> 4) * 8) * 2;
            ldsm4(qf[m][kd], aq);
        }

    float oacc[2][8][4];
#pragma unroll
    for (int m = 0; m < 2; m++)
#pragma unroll
        for (int i = 0; i < 8; i++)
#pragma unroll
            for (int j = 0; j < 4; j++) oacc[m][i][j] = 0.f;
    float lacc[2][4];                        // row sums via ones-mma
#pragma unroll
    for (int m = 0; m < 2; m++)
#pragma unroll
        for (int j = 0; j < 4; j++) lacc[m][j] = 0.f;

    const uint32_t bones[2] = { 0x3C003C00u, 0x3C003C00u };   // fp16 1.0 x4
    const int* mflag_p = g_mflag + (b * 16 + blockIdx.x) * 32;

    const int NT = T_ / KV_ROWS;  // 16
    for (int kt = 0; kt < NT; kt++) {
        CP_WAIT0();                          // this thread's copies of stage kt&1 done
        __syncthreads();                     // all threads' copies visible; stage (kt+1)&1 free
        if (kt + 1 < NT) {
            prefetch(kgn, vgn, stg[(kt + 1) & 1]);
            CP_COMMIT();
            kgn += (size_t)KV_ROWS * C_; vgn += (size_t)KV_ROWS * C_;
        }

        const uint32_t kS = stg[kt & 1];
        const uint32_t vS = kS + KV_ROWS * AT_ROWB;
        const int flag = mflag_p[2 * kt] & mflag_p[2 * kt + 1];

        uint32_t pf[2][2][4];                // [m][chunk ring slot][frag]

        // S-phase for one j-column (8 keys), j in 0..15 over the 128-key stage.
        auto s_phase = [&](int j, int masked){
            uint32_t kb0[4], kb1[4];
            uint32_t a0 = kS + (j * 8 + (lane & 7)) * AT_ROWB + (lane >> 3) * 16;
            ldsm4(kb0, a0);
            ldsm4(kb1, a0 + 64);
            const int slot = (j >> 1) & 1;
#pragma unroll
            for (int m = 0; m < 2; m++) {
                float sj[4] = {0.f, 0.f, 0.f, 0.f};
                mma16816(sj, qf[m][0], kb0 + 0);
                mma16816(sj, qf[m][1], kb0 + 2);
                mma16816(sj, qf[m][2], kb1 + 0);
                mma16816(sj, qf[m][3], kb1 + 2);

                float e0 = ex2f(sj[0]);
                float e1 = ex2f(sj[1]);
                float e2 = ex2f(sj[2]);
                float e3 = ex2f(sj[3]);
                if (masked) {
                    const int* mp = mask
                        + ((size_t)b * T_ + q0 + w * 32 + m * 16 + (lane >> 2)) * T_
                        + kt * KV_ROWS + j * 8 + 2 * (lane & 3);
                    int2 m0v = *(const int2*)mp;
                    int2 m1v = *(const int2*)(mp + 8 * T_);
                    if (m0v.x == 0) e0 = 0.f;
                    if (m0v.y == 0) e1 = 0.f;
                    if (m1v.x == 0) e2 = 0.f;
                    if (m1v.y == 0) e3 = 0.f;
                }
                pf[m][slot][(j & 1) * 2 + 0] = packe(e0, e1);
                pf[m][slot][(j & 1) * 2 + 1] = packe(e2, e3);
            }
        };

        // PV-phase for chunk c (16 keys): O += P V ; l += P 1. Reads slot c&1.
        auto pv_phase = [&](int c){
            const int slot = c & 1;
#pragma unroll
            for (int np = 0; np < 4; np++) {
                uint32_t vb[4];
                uint32_t ad = vS + (c * 16 + ((lane >> 3) & 1) * 8 + (lane & 7)) * AT_ROWB
                            + (np * 16 + (lane >> 4) * 8) * 2;
                ldsm4t(vb, ad);
#pragma unroll
                for (int m = 0; m < 2; m++) {
                    mma16816(oacc[m][np * 2 + 0], pf[m][slot], vb + 0);
                    mma16816(oacc[m][np * 2 + 1], pf[m][slot], vb + 2);
                }
            }
#pragma unroll
            for (int m = 0; m < 2; m++)
                mma16816(lacc[m], pf[m][slot], bones);
        };

        // Chunk-ring pipeline: s(c+1) fills slot (c+1)&1 while pv(c) drains slot c&1.
        if (flag) {
            s_phase(0, 0); s_phase(1, 0);
#pragma unroll
            for (int c = 0; c < 8; c++) {
                if (c < 7) { s_phase(2 * c + 2, 0); s_phase(2 * c + 3, 0); }
                pv_phase(c);
            }
        } else {
            s_phase(0, 1); s_phase(1, 1);
#pragma unroll
            for (int c = 0; c < 8; c++) {
                if (c < 7) { s_phase(2 * c + 2, 1); s_phase(2 * c + 3, 1); }
                pv_phase(c);
            }
        }
    }

    // ---- normalize and write (row sums replicated across quad lanes) ----
#pragma unroll
    for (int m = 0; m < 2; m++) {
        const float inv0 = 1.f / lacc[m][0];
        const float inv1 = 1.f / lacc[m][2];

        size_t o0 = (size_t)(b * T_ + q0 + w * 32 + m * 16 + (lane >> 2)) * C_
                  + h * D_ + 2 * (lane & 3);
        size_t o1 = o0 + 8 * C_;
#pragma unroll
        for (int nd = 0; nd < 8; nd++) {
            *(__half2*)(Oh + o0 + nd * 8) =
                __floats2half2_rn(oacc[m][nd][0] * inv0, oacc[m][nd][1] * inv0);
            *(__half2*)(Oh + o1 + nd * 8) =
                __floats2half2_rn(oacc[m][nd][2] * inv1, oacc[m][nd][3] * inv1);
        }
    }
}

// ===========================================================================
extern "C" void kernel_launch(void* const* d_in, const int* in_sizes, int n_in,
                              void* d_out, int out_size)
{
    const float* x    = (const float*)d_in[0];
    const int*   mask = (const int*)  d_in[1];
    const float* Wq   = (const float*)d_in[2];
    const float* Wk   = (const float*)d_in[3];
    const float* Wv   = (const float*)d_in[4];
    const float* Wo   = (const float*)d_in[5];
    float* out = (float*)d_out;

    __half *Qh, *Kh, *Vh, *xh, *wh, *Oh;
    cudaGetSymbolAddress((void**)&Qh, g_Qh);
    cudaGetSymbolAddress((void**)&Kh, g_Kh);
    cudaGetSymbolAddress((void**)&Vh, g_Vh);
    cudaGetSymbolAddress((void**)&xh, g_xh);
    cudaGetSymbolAddress((void**)&wh, g_wh);
    cudaGetSymbolAddress((void**)&Oh, g_Oh);

    cudaFuncSetAttribute((const void*)gemm_fp16<true>,
                         cudaFuncAttributeMaxDynamicSharedMemorySize, G_SMEM);
    cudaFuncSetAttribute((const void*)gemm_fp16<false>,
                         cudaFuncAttributeMaxDynamicSharedMemorySize, G_SMEM);
    cudaFuncSetAttribute(attn_reg, cudaFuncAttributeMaxDynamicSharedMemorySize, ATT_SMEM);

    convert_all<<<(XN_ + 4 * WN_) / 1024, 256>>>(x, Wq, Wk, Wv, Wo, xh, wh);
    mask_flags<<<B_ * 16 * 32, 256>>>(mask);

    dim3 gq(C_ / 128, M_ / 128, 3);   // fused QKV, single-pass fp16 (Q scaled)
    gemm_fp16<true><<<gq, 128, G_SMEM>>>(xh, wh, Qh, Kh, Vh, M_, C_, C_);

    dim3 ga(T_ / 128, B_ * H_);       // (16, 64)
    attn_reg<<<ga, 128, ATT_SMEM>>>(Qh, Kh, Vh, mask, Oh);

    dim3 go(C_ / 128, M_ / 128, 1);   // out-proj, single-pass fp16
    gemm_fp16<false><<<go, 128, G_SMEM>>>(Oh, wh + 3 * (size_t)WN_,
                                          out, out, out, M_, C_, C_);
}